// round 1
// baseline (speedup 1.0000x reference)
#include <cuda_runtime.h>
#include <math.h>

#define Bsz 2
#define C 256
#define NTOK 4096
#define G 8
#define CPG 32
#define NH 4
#define HD 64
#define EPS 1e-5f
#define SCALE 0.125f

// ---------------- scratch (device globals; no allocations allowed) ----------------
__device__ float g_qkv[(size_t)Bsz * 3 * NH * NTOK * HD];   // [b][which][h][n][d] token-major
__device__ float g_ao [(size_t)Bsz * NTOK * C];             // [b][n][c] token-major
__device__ float g_sA [Bsz * C];                            // per (b,c) scale
__device__ float g_tA [Bsz * C];                            // per (b,c) shift

// 16B-chunk XOR swizzle for 64-float rows: conflict-free col- and row-strided access
#define SWZ(row, c4) (((row) << 6) + ((((c4) ^ ((row) >> 2)) & 15) << 2))

// ---------------- kernel A: groupnorm stats + affine coefficients ----------------
__global__ void gn_stats_kernel(const float* __restrict__ x,
                                const float* __restrict__ nw,
                                const float* __restrict__ nb) {
    int bg = blockIdx.x;            // 0..15 = b*G+g
    int tid = threadIdx.x;
    const float4* p = reinterpret_cast<const float4*>(x + (size_t)bg * (CPG * NTOK));
    float s = 0.f, ss = 0.f;
    const int n4 = (CPG * NTOK) / 4;
    for (int i = tid; i < n4; i += 256) {
        float4 v = p[i];
        s  += v.x + v.y + v.z + v.w;
        ss += v.x * v.x + v.y * v.y + v.z * v.z + v.w * v.w;
    }
    #pragma unroll
    for (int o = 16; o > 0; o >>= 1) {
        s  += __shfl_xor_sync(0xffffffffu, s, o);
        ss += __shfl_xor_sync(0xffffffffu, ss, o);
    }
    __shared__ float rs[8], rss[8];
    __shared__ float sh_mean, sh_rstd;
    if ((tid & 31) == 0) { rs[tid >> 5] = s; rss[tid >> 5] = ss; }
    __syncthreads();
    if (tid == 0) {
        float S = 0.f, SS = 0.f;
        #pragma unroll
        for (int i = 0; i < 8; i++) { S += rs[i]; SS += rss[i]; }
        const float inv = 1.f / (float)(CPG * NTOK);
        float mean = S * inv;
        float var  = SS * inv - mean * mean;
        sh_mean = mean;
        sh_rstd = rsqrtf(var + EPS);
    }
    __syncthreads();
    if (tid < CPG) {
        int b = bg / G, g = bg % G;
        int c = g * CPG + tid;
        float sA = sh_rstd * nw[c];
        g_sA[b * C + c] = sA;
        g_tA[b * C + c] = nb[c] - sh_mean * sA;
    }
}

// ---------------- kernel B: fused groupnorm-affine + QKV GEMM ----------------
// y[b,o,n] = sum_c W[o,c]*(x[b,c,n]*sA + tA) + bias[o], written token-major into g_qkv
__global__ __launch_bounds__(256) void qkv_kernel(const float* __restrict__ x,
                                                  const float* __restrict__ W,
                                                  const float* __restrict__ bias) {
    __shared__ float As[16][64];   // As[k][m]  (transposed W tile)
    __shared__ float Bs[16][64];   // Bs[k][n]  (normalized x tile)
    int tid = threadIdx.x;
    int tx = tid & 15, ty = tid >> 4;
    int n0 = blockIdx.x * 64, m0 = blockIdx.y * 64, b = blockIdx.z;
    float acc[4][4] = {};
    int arow = tid >> 2, akc = (tid & 3) << 2;     // A loader: 64 rows x 4 k-chunks
    int bkr  = tid >> 4, bnc = (tid & 15) << 2;    // B loader: 16 rows x 16 n-chunks

    for (int k0 = 0; k0 < C; k0 += 16) {
        float4 w4 = *reinterpret_cast<const float4*>(W + (size_t)(m0 + arow) * C + k0 + akc);
        int ch = k0 + bkr;
        float sA = g_sA[b * C + ch], tA = g_tA[b * C + ch];
        float4 xv = *reinterpret_cast<const float4*>(x + ((size_t)b * C + ch) * NTOK + n0 + bnc);
        As[akc + 0][arow] = w4.x; As[akc + 1][arow] = w4.y;
        As[akc + 2][arow] = w4.z; As[akc + 3][arow] = w4.w;
        *reinterpret_cast<float4*>(&Bs[bkr][bnc]) =
            make_float4(fmaf(xv.x, sA, tA), fmaf(xv.y, sA, tA),
                        fmaf(xv.z, sA, tA), fmaf(xv.w, sA, tA));
        __syncthreads();
        #pragma unroll
        for (int k = 0; k < 16; k++) {
            float4 a4 = *reinterpret_cast<const float4*>(&As[k][ty << 2]);
            float4 b4 = *reinterpret_cast<const float4*>(&Bs[k][tx << 2]);
            float ar[4] = {a4.x, a4.y, a4.z, a4.w};
            float br[4] = {b4.x, b4.y, b4.z, b4.w};
            #pragma unroll
            for (int r = 0; r < 4; r++)
                #pragma unroll
                for (int c = 0; c < 4; c++)
                    acc[r][c] = fmaf(ar[r], br[c], acc[r][c]);
        }
        __syncthreads();
    }

    // epilogue: token-major store. which/h constant per block row (m tile = 64)
    int which = blockIdx.y >> 2;     // 0=q,1=k,2=v
    int hh    = blockIdx.y & 3;
    int d0    = ty << 2;             // d = ty*4 + r
    float qb[4];
    #pragma unroll
    for (int r = 0; r < 4; r++) qb[r] = bias[m0 + d0 + r];
    size_t base = ((size_t)(b * 3 + which) * NH + hh) * NTOK;
    #pragma unroll
    for (int c = 0; c < 4; c++) {
        int n = n0 + (tx << 2) + c;
        float4 o = make_float4(acc[0][c] + qb[0], acc[1][c] + qb[1],
                               acc[2][c] + qb[2], acc[3][c] + qb[3]);
        *reinterpret_cast<float4*>(g_qkv + (base + n) * HD + d0) = o;
    }
}

// ---------------- kernel C: flash attention (fp32, online softmax) ----------------
#define ATTN_SMEM ((3 * 4096 + 64 * 68) * 4)   // Qs,Ks,Vs swizzled [64][64] + Ps[64][68]
__global__ __launch_bounds__(256) void attn_kernel() {
    extern __shared__ float sm[];
    float* Qs = sm;
    float* Ks = sm + 4096;
    float* Vs = sm + 8192;
    float* Ps = sm + 12288;   // [64][68]
    int tid = threadIdx.x;
    int tx = tid & 15, ty = tid >> 4;
    int qn0 = blockIdx.x * 64;
    int b = blockIdx.y >> 2, h = blockIdx.y & 3;

    const float* qg = g_qkv + (((size_t)(b * 3 + 0) * NH + h) * NTOK + qn0) * HD;
    const float* kg = g_qkv + (((size_t)(b * 3 + 1) * NH + h) * NTOK) * HD;
    const float* vg = g_qkv + (((size_t)(b * 3 + 2) * NH + h) * NTOK) * HD;

    for (int i = tid; i < 1024; i += 256) {
        int r = i >> 4, c4 = i & 15;
        float4 v = *reinterpret_cast<const float4*>(qg + r * HD + (c4 << 2));
        *reinterpret_cast<float4*>(Qs + SWZ(r, c4)) =
            make_float4(v.x * SCALE, v.y * SCALE, v.z * SCALE, v.w * SCALE);
    }

    float o_acc[4][4] = {};
    float rmax[4] = {-1e30f, -1e30f, -1e30f, -1e30f};
    float rsum[4] = {};

    for (int kt = 0; kt < NTOK / 64; kt++) {
        const float* kp = kg + (size_t)(kt * 64) * HD;
        const float* vp = vg + (size_t)(kt * 64) * HD;
        for (int i = tid; i < 1024; i += 256) {
            int r = i >> 4, c4 = i & 15;
            *reinterpret_cast<float4*>(Ks + SWZ(r, c4)) =
                *reinterpret_cast<const float4*>(kp + r * HD + (c4 << 2));
            *reinterpret_cast<float4*>(Vs + SWZ(r, c4)) =
                *reinterpret_cast<const float4*>(vp + r * HD + (c4 << 2));
        }
        __syncthreads();

        // S = Q K^T  (dot-form over d)
        float s_acc[4][4] = {};
        #pragma unroll
        for (int c4 = 0; c4 < 16; c4++) {
            float4 af[4], bf[4];
            #pragma unroll
            for (int r = 0; r < 4; r++)
                af[r] = *reinterpret_cast<const float4*>(Qs + SWZ((ty << 2) + r, c4));
            #pragma unroll
            for (int c = 0; c < 4; c++)
                bf[c] = *reinterpret_cast<const float4*>(Ks + SWZ((tx << 2) + c, c4));
            #pragma unroll
            for (int r = 0; r < 4; r++)
                #pragma unroll
                for (int c = 0; c < 4; c++)
                    s_acc[r][c] = fmaf(af[r].x, bf[c].x,
                                  fmaf(af[r].y, bf[c].y,
                                  fmaf(af[r].z, bf[c].z,
                                  fmaf(af[r].w, bf[c].w, s_acc[r][c]))));
        }

        // online softmax (row reduce across the 16 tx lanes of the row)
        #pragma unroll
        for (int r = 0; r < 4; r++) {
            float m = fmaxf(fmaxf(s_acc[r][0], s_acc[r][1]),
                            fmaxf(s_acc[r][2], s_acc[r][3]));
            #pragma unroll
            for (int o = 8; o > 0; o >>= 1)
                m = fmaxf(m, __shfl_xor_sync(0xffffffffu, m, o));
            float mnew  = fmaxf(rmax[r], m);
            float alpha = __expf(rmax[r] - mnew);
            rmax[r] = mnew;
            float p0 = __expf(s_acc[r][0] - mnew);
            float p1 = __expf(s_acc[r][1] - mnew);
            float p2 = __expf(s_acc[r][2] - mnew);
            float p3 = __expf(s_acc[r][3] - mnew);
            rsum[r] = rsum[r] * alpha + (p0 + p1 + p2 + p3);
            #pragma unroll
            for (int c = 0; c < 4; c++) o_acc[r][c] *= alpha;
            *reinterpret_cast<float4*>(Ps + ((ty << 2) + r) * 68 + (tx << 2)) =
                make_float4(p0, p1, p2, p3);
        }
        __syncthreads();

        // O += P @ V  (outer-form over m; Ps broadcast, Vs swizzled float4)
        const float* pr0 = Ps + ((ty << 2) + 0) * 68;
        const float* pr1 = Ps + ((ty << 2) + 1) * 68;
        const float* pr2 = Ps + ((ty << 2) + 2) * 68;
        const float* pr3 = Ps + ((ty << 2) + 3) * 68;
        #pragma unroll 8
        for (int m = 0; m < 64; m++) {
            float4 bv = *reinterpret_cast<const float4*>(Vs + SWZ(m, tx));
            float a0 = pr0[m], a1 = pr1[m], a2 = pr2[m], a3 = pr3[m];
            o_acc[0][0] = fmaf(a0, bv.x, o_acc[0][0]); o_acc[0][1] = fmaf(a0, bv.y, o_acc[0][1]);
            o_acc[0][2] = fmaf(a0, bv.z, o_acc[0][2]); o_acc[0][3] = fmaf(a0, bv.w, o_acc[0][3]);
            o_acc[1][0] = fmaf(a1, bv.x, o_acc[1][0]); o_acc[1][1] = fmaf(a1, bv.y, o_acc[1][1]);
            o_acc[1][2] = fmaf(a1, bv.z, o_acc[1][2]); o_acc[1][3] = fmaf(a1, bv.w, o_acc[1][3]);
            o_acc[2][0] = fmaf(a2, bv.x, o_acc[2][0]); o_acc[2][1] = fmaf(a2, bv.y, o_acc[2][1]);
            o_acc[2][2] = fmaf(a2, bv.z, o_acc[2][2]); o_acc[2][3] = fmaf(a2, bv.w, o_acc[2][3]);
            o_acc[3][0] = fmaf(a3, bv.x, o_acc[3][0]); o_acc[3][1] = fmaf(a3, bv.y, o_acc[3][1]);
            o_acc[3][2] = fmaf(a3, bv.z, o_acc[3][2]); o_acc[3][3] = fmaf(a3, bv.w, o_acc[3][3]);
        }
        __syncthreads();
    }

    // normalize + store token-major [b][n][c]
    #pragma unroll
    for (int r = 0; r < 4; r++) {
        float l = rsum[r];
        #pragma unroll
        for (int o = 8; o > 0; o >>= 1) l += __shfl_xor_sync(0xffffffffu, l, o);
        float inv = 1.f / l;
        float* dst = g_ao + ((size_t)b * NTOK + qn0 + (ty << 2) + r) * C + h * HD + (tx << 2);
        *reinterpret_cast<float4*>(dst) =
            make_float4(o_acc[r][0] * inv, o_acc[r][1] * inv,
                        o_acc[r][2] * inv, o_acc[r][3] * inv);
    }
}

// ---------------- kernel D: proj GEMM + bias + residual ----------------
__global__ __launch_bounds__(256) void proj_kernel(const float* __restrict__ x,
                                                   const float* __restrict__ W,
                                                   const float* __restrict__ bias,
                                                   float* __restrict__ out) {
    __shared__ float As[4096];   // swizzled [token][c-chunk]
    __shared__ float Ws[4096];   // swizzled [outch][c-chunk]
    int tid = threadIdx.x;
    int tx = tid & 15, ty = tid >> 4;
    int n0 = blockIdx.x * 64, o0 = blockIdx.y * 64, b = blockIdx.z;
    float acc[4][4] = {};

    for (int c0 = 0; c0 < C; c0 += 64) {
        for (int i = tid; i < 1024; i += 256) {
            int r = i >> 4, c4 = i & 15;
            *reinterpret_cast<float4*>(As + SWZ(r, c4)) =
                *reinterpret_cast<const float4*>(g_ao + ((size_t)b * NTOK + n0 + r) * C + c0 + (c4 << 2));
            *reinterpret_cast<float4*>(Ws + SWZ(r, c4)) =
                *reinterpret_cast<const float4*>(W + (size_t)(o0 + r) * C + c0 + (c4 << 2));
        }
        __syncthreads();
        #pragma unroll
        for (int c4 = 0; c4 < 16; c4++) {
            float4 af[4], wf[4];
            #pragma unroll
            for (int r = 0; r < 4; r++)
                af[r] = *reinterpret_cast<const float4*>(As + SWZ((ty << 2) + r, c4));
            #pragma unroll
            for (int c = 0; c < 4; c++)
                wf[c] = *reinterpret_cast<const float4*>(Ws + SWZ((tx << 2) + c, c4));
            #pragma unroll
            for (int r = 0; r < 4; r++)
                #pragma unroll
                for (int c = 0; c < 4; c++)
                    acc[r][c] = fmaf(af[r].x, wf[c].x,
                                fmaf(af[r].y, wf[c].y,
                                fmaf(af[r].z, wf[c].z,
                                fmaf(af[r].w, wf[c].w, acc[r][c]))));
        }
        __syncthreads();
    }

    // out[b,o,n] = acc + bias[o] + x[b,o,n]   (r = token, c = outch)
    #pragma unroll
    for (int c = 0; c < 4; c++) {
        int o = o0 + (tx << 2) + c;
        float pb = bias[o];
        size_t idx = ((size_t)b * C + o) * NTOK + n0 + (ty << 2);
        float4 xv = *reinterpret_cast<const float4*>(x + idx);
        float4 ov = make_float4(acc[0][c] + pb + xv.x, acc[1][c] + pb + xv.y,
                                acc[2][c] + pb + xv.z, acc[3][c] + pb + xv.w);
        *reinterpret_cast<float4*>(out + idx) = ov;
    }
}

// ---------------- launch ----------------
extern "C" void kernel_launch(void* const* d_in, const int* in_sizes, int n_in,
                              void* d_out, int out_size) {
    const float* x      = (const float*)d_in[0];
    const float* norm_w = (const float*)d_in[1];
    const float* norm_b = (const float*)d_in[2];
    const float* qkv_w  = (const float*)d_in[3];
    const float* qkv_b  = (const float*)d_in[4];
    const float* proj_w = (const float*)d_in[5];
    const float* proj_b = (const float*)d_in[6];
    float* out = (float*)d_out;

    cudaFuncSetAttribute(attn_kernel, cudaFuncAttributeMaxDynamicSharedMemorySize, ATTN_SMEM);

    gn_stats_kernel<<<Bsz * G, 256>>>(x, norm_w, norm_b);
    qkv_kernel<<<dim3(NTOK / 64, (3 * C) / 64, Bsz), 256>>>(x, qkv_w, qkv_b);
    attn_kernel<<<dim3(NTOK / 64, Bsz * NH), 256, ATTN_SMEM>>>();
    proj_kernel<<<dim3(NTOK / 64, C / 64, Bsz), 256>>>(x, proj_w, proj_b, out);
}

// round 2
// speedup vs baseline: 4.1181x; 4.1181x over previous
#include <cuda_runtime.h>
#include <math.h>
#include <stdint.h>

#define Bsz 2
#define C 256
#define NTOK 4096
#define G 8
#define CPG 32
#define NH 4
#define HD 64
#define EPS 1e-5f
#define SCALE 0.125f
#define LOG2E 1.4426950408889634f

// ---------------- scratch (device globals; no allocations allowed) ----------------
__device__ uint16_t g_qkv[(size_t)Bsz * 3 * NH * NTOK * HD];  // bf16 [b][qkv][h][n][d]
__device__ float    g_ao [(size_t)Bsz * NTOK * C];            // fp32 [b][n][c]
__device__ float    g_sA [Bsz * C];
__device__ float    g_tA [Bsz * C];

// 16B-chunk XOR swizzle for 64-float rows (fp32 GEMM tiles)
#define SWZ(row, c4) (((row) << 6) + ((((c4) ^ ((row) >> 2)) & 15) << 2))

// ---------------- PTX helpers ----------------
__device__ __forceinline__ uint32_t f2bf2(float lo, float hi) {
    uint32_t r;
    asm("cvt.rn.bf16x2.f32 %0, %1, %2;" : "=r"(r) : "f"(hi), "f"(lo));
    return r;
}
__device__ __forceinline__ float ex2(float x) {
    float y; asm("ex2.approx.ftz.f32 %0, %1;" : "=f"(y) : "f"(x)); return y;
}
__device__ __forceinline__ void ldmx4(uint32_t& r0, uint32_t& r1, uint32_t& r2, uint32_t& r3,
                                      uint32_t addr) {
    asm volatile("ldmatrix.sync.aligned.m8n8.x4.shared.b16 {%0,%1,%2,%3}, [%4];"
                 : "=r"(r0), "=r"(r1), "=r"(r2), "=r"(r3) : "r"(addr));
}
__device__ __forceinline__ void ldmx4t(uint32_t& r0, uint32_t& r1, uint32_t& r2, uint32_t& r3,
                                       uint32_t addr) {
    asm volatile("ldmatrix.sync.aligned.m8n8.x4.trans.shared.b16 {%0,%1,%2,%3}, [%4];"
                 : "=r"(r0), "=r"(r1), "=r"(r2), "=r"(r3) : "r"(addr));
}
__device__ __forceinline__ void mma16816(float* c, const uint32_t* a, uint32_t b0, uint32_t b1) {
    asm volatile(
        "mma.sync.aligned.m16n8k16.row.col.f32.bf16.bf16.f32 "
        "{%0,%1,%2,%3}, {%4,%5,%6,%7}, {%8,%9}, {%0,%1,%2,%3};"
        : "+f"(c[0]), "+f"(c[1]), "+f"(c[2]), "+f"(c[3])
        : "r"(a[0]), "r"(a[1]), "r"(a[2]), "r"(a[3]), "r"(b0), "r"(b1));
}

// ---------------- kernel A: groupnorm stats + affine coefficients ----------------
__global__ void gn_stats_kernel(const float* __restrict__ x,
                                const float* __restrict__ nw,
                                const float* __restrict__ nb) {
    int bg = blockIdx.x;
    int tid = threadIdx.x;
    const float4* p = reinterpret_cast<const float4*>(x + (size_t)bg * (CPG * NTOK));
    float s = 0.f, ss = 0.f;
    const int n4 = (CPG * NTOK) / 4;
    for (int i = tid; i < n4; i += 256) {
        float4 v = p[i];
        s  += v.x + v.y + v.z + v.w;
        ss += v.x * v.x + v.y * v.y + v.z * v.z + v.w * v.w;
    }
    #pragma unroll
    for (int o = 16; o > 0; o >>= 1) {
        s  += __shfl_xor_sync(0xffffffffu, s, o);
        ss += __shfl_xor_sync(0xffffffffu, ss, o);
    }
    __shared__ float rs[8], rss[8];
    __shared__ float sh_mean, sh_rstd;
    if ((tid & 31) == 0) { rs[tid >> 5] = s; rss[tid >> 5] = ss; }
    __syncthreads();
    if (tid == 0) {
        float S = 0.f, SS = 0.f;
        #pragma unroll
        for (int i = 0; i < 8; i++) { S += rs[i]; SS += rss[i]; }
        const float inv = 1.f / (float)(CPG * NTOK);
        float mean = S * inv;
        float var  = SS * inv - mean * mean;
        sh_mean = mean;
        sh_rstd = rsqrtf(var + EPS);
    }
    __syncthreads();
    if (tid < CPG) {
        int b = bg / G, g = bg % G;
        int c = g * CPG + tid;
        float sA = sh_rstd * nw[c];
        g_sA[b * C + c] = sA;
        g_tA[b * C + c] = nb[c] - sh_mean * sA;
    }
}

// ---------------- kernel B: fused groupnorm-affine + QKV GEMM (fp32 -> bf16 out) ---
__global__ __launch_bounds__(256) void qkv_kernel(const float* __restrict__ x,
                                                  const float* __restrict__ W,
                                                  const float* __restrict__ bias) {
    __shared__ float As[16][64];
    __shared__ float Bs[16][64];
    int tid = threadIdx.x;
    int tx = tid & 15, ty = tid >> 4;
    int n0 = blockIdx.x * 64, m0 = blockIdx.y * 64, b = blockIdx.z;
    float acc[4][4] = {};
    int arow = tid >> 2, akc = (tid & 3) << 2;
    int bkr  = tid >> 4, bnc = (tid & 15) << 2;

    for (int k0 = 0; k0 < C; k0 += 16) {
        float4 w4 = *reinterpret_cast<const float4*>(W + (size_t)(m0 + arow) * C + k0 + akc);
        int ch = k0 + bkr;
        float sA = g_sA[b * C + ch], tA = g_tA[b * C + ch];
        float4 xv = *reinterpret_cast<const float4*>(x + ((size_t)b * C + ch) * NTOK + n0 + bnc);
        As[akc + 0][arow] = w4.x; As[akc + 1][arow] = w4.y;
        As[akc + 2][arow] = w4.z; As[akc + 3][arow] = w4.w;
        *reinterpret_cast<float4*>(&Bs[bkr][bnc]) =
            make_float4(fmaf(xv.x, sA, tA), fmaf(xv.y, sA, tA),
                        fmaf(xv.z, sA, tA), fmaf(xv.w, sA, tA));
        __syncthreads();
        #pragma unroll
        for (int k = 0; k < 16; k++) {
            float4 a4 = *reinterpret_cast<const float4*>(&As[k][ty << 2]);
            float4 b4 = *reinterpret_cast<const float4*>(&Bs[k][tx << 2]);
            float ar[4] = {a4.x, a4.y, a4.z, a4.w};
            float br[4] = {b4.x, b4.y, b4.z, b4.w};
            #pragma unroll
            for (int r = 0; r < 4; r++)
                #pragma unroll
                for (int c = 0; c < 4; c++)
                    acc[r][c] = fmaf(ar[r], br[c], acc[r][c]);
        }
        __syncthreads();
    }

    int which = blockIdx.y >> 2;
    int hh    = blockIdx.y & 3;
    int d0    = ty << 2;
    // q gets folded softmax scale (in log2 domain)
    float qs = (which == 0) ? (SCALE * LOG2E) : 1.f;
    float qb[4];
    #pragma unroll
    for (int r = 0; r < 4; r++) qb[r] = bias[m0 + d0 + r];
    size_t base = ((size_t)(b * 3 + which) * NH + hh) * NTOK;
    #pragma unroll
    for (int c = 0; c < 4; c++) {
        int n = n0 + (tx << 2) + c;
        float v0 = (acc[0][c] + qb[0]) * qs;
        float v1 = (acc[1][c] + qb[1]) * qs;
        float v2 = (acc[2][c] + qb[2]) * qs;
        float v3 = (acc[3][c] + qb[3]) * qs;
        uint2 pkd = make_uint2(f2bf2(v0, v1), f2bf2(v2, v3));
        *reinterpret_cast<uint2*>(g_qkv + (base + n) * HD + d0) = pkd;
    }
}

// ---------------- kernel C: flash attention (bf16 mma.sync, online softmax) -------
// Br=128 (8 warps x m16), Bc=64.  smem tiles swizzled in 16B chunks: ch ^= row&7
__global__ __launch_bounds__(256, 2) void attn_kernel() {
    __shared__ __align__(16) uint16_t Ks[64 * 64];
    __shared__ __align__(16) uint16_t Vs[64 * 64];
    __shared__ __align__(16) uint16_t Qs[128 * 64];
    int tid = threadIdx.x;
    int w = tid >> 5, lane = tid & 31;
    int qn0 = blockIdx.x * 128;
    int b = blockIdx.y >> 2, h = blockIdx.y & 3;

    const uint16_t* qg = g_qkv + (((size_t)(b * 3 + 0) * NH + h) * NTOK + qn0) * HD;
    const uint16_t* kg = g_qkv + (((size_t)(b * 3 + 1) * NH + h) * NTOK) * HD;
    const uint16_t* vg = g_qkv + (((size_t)(b * 3 + 2) * NH + h) * NTOK) * HD;

    // load Q tile 128x64 (bf16), swizzled
    for (int i = tid; i < 1024; i += 256) {
        int r = i >> 3, ch = i & 7;
        uint4 v = *reinterpret_cast<const uint4*>(qg + r * 64 + ch * 8);
        *reinterpret_cast<uint4*>((char*)Qs + r * 128 + (((ch ^ (r & 7)) & 7) << 4)) = v;
    }
    __syncthreads();

    uint32_t qbase = (uint32_t)__cvta_generic_to_shared(Qs);
    uint32_t kbase = (uint32_t)__cvta_generic_to_shared(Ks);
    uint32_t vbase = (uint32_t)__cvta_generic_to_shared(Vs);
    int l8 = lane & 7, ggg = lane >> 3;
    int gLo = ggg & 1, gHi = ggg >> 1;

    // Q fragments: A-frag groups: (rows+0,klo)(rows+8,klo)(rows+0,khi)(rows+8,khi)
    uint32_t qf[4][4];
    {
        int row = w * 16 + gLo * 8 + l8;   // careful: A group order uses (ggg&1)->rows? no:
        // A-frag: g0 rows0-7 klo, g1 rows8-15 klo, g2 rows0-7 khi, g3 rows8-15 khi
        row = w * 16 + (ggg & 1) * 8 + l8;
        #pragma unroll
        for (int kk = 0; kk < 4; kk++) {
            int ch = kk * 2 + (ggg >> 1);
            ldmx4(qf[kk][0], qf[kk][1], qf[kk][2], qf[kk][3],
                  qbase + row * 128 + (((ch ^ (row & 7)) & 7) << 4));
        }
    }
    __syncthreads();

    // address offsets for K (B-frag: g0 keys0-7 dlo, g1 keys0-7 dhi, g2 keys8-15 dlo, g3 hi)
    int krow_off = gHi * 8 + l8;   // + nb2*16
    // V trans (g0 keys0-7 d0, g1 keys8-15 d0, g2 keys0-7 d8, g3 keys8-15 d8)
    int vrow_off = gLo * 8 + l8;   // + kk*16

    float o[8][4] = {};
    float rmax0 = -1e30f, rmax1 = -1e30f, rsum0 = 0.f, rsum1 = 0.f;

    for (int kt = 0; kt < NTOK / 64; kt++) {
        const uint16_t* kp = kg + (size_t)kt * 64 * 64;
        const uint16_t* vp = vg + (size_t)kt * 64 * 64;
        for (int i = tid; i < 512; i += 256) {
            int r = i >> 3, ch = i & 7;
            int so = r * 128 + (((ch ^ (r & 7)) & 7) << 4);
            *reinterpret_cast<uint4*>((char*)Ks + so) =
                *reinterpret_cast<const uint4*>(kp + r * 64 + ch * 8);
            *reinterpret_cast<uint4*>((char*)Vs + so) =
                *reinterpret_cast<const uint4*>(vp + r * 64 + ch * 8);
        }
        __syncthreads();

        // S = Q K^T : sc[nb] covers keys nb*8..nb*8+7
        float sc[8][4] = {};
        #pragma unroll
        for (int nb2 = 0; nb2 < 4; nb2++) {
            #pragma unroll
            for (int kk = 0; kk < 4; kk++) {
                int row = nb2 * 16 + krow_off;
                int ch = kk * 2 + gLo;
                uint32_t b0, b1, b2, b3;
                ldmx4(b0, b1, b2, b3, kbase + row * 128 + (((ch ^ (row & 7)) & 7) << 4));
                mma16816(sc[2 * nb2],     qf[kk], b0, b1);
                mma16816(sc[2 * nb2 + 1], qf[kk], b2, b3);
            }
        }

        // online softmax (log2 domain; q pre-scaled by 0.125*log2e)
        float m0 = -1e30f, m1 = -1e30f;
        #pragma unroll
        for (int nb = 0; nb < 8; nb++) {
            m0 = fmaxf(m0, fmaxf(sc[nb][0], sc[nb][1]));
            m1 = fmaxf(m1, fmaxf(sc[nb][2], sc[nb][3]));
        }
        m0 = fmaxf(m0, __shfl_xor_sync(0xffffffffu, m0, 1));
        m0 = fmaxf(m0, __shfl_xor_sync(0xffffffffu, m0, 2));
        m1 = fmaxf(m1, __shfl_xor_sync(0xffffffffu, m1, 1));
        m1 = fmaxf(m1, __shfl_xor_sync(0xffffffffu, m1, 2));
        float mn0 = fmaxf(rmax0, m0), mn1 = fmaxf(rmax1, m1);
        float al0 = ex2(rmax0 - mn0), al1 = ex2(rmax1 - mn1);
        rmax0 = mn0; rmax1 = mn1;
        float ps0 = 0.f, ps1 = 0.f;
        #pragma unroll
        for (int nb = 0; nb < 8; nb++) {
            sc[nb][0] = ex2(sc[nb][0] - mn0);
            sc[nb][1] = ex2(sc[nb][1] - mn0);
            sc[nb][2] = ex2(sc[nb][2] - mn1);
            sc[nb][3] = ex2(sc[nb][3] - mn1);
            ps0 += sc[nb][0] + sc[nb][1];
            ps1 += sc[nb][2] + sc[nb][3];
            o[nb][0] *= al0; o[nb][1] *= al0;
            o[nb][2] *= al1; o[nb][3] *= al1;
        }
        rsum0 = rsum0 * al0 + ps0;
        rsum1 = rsum1 * al1 + ps1;

        // pack P (c-frag -> a-frag, no smem round trip)
        uint32_t pa[4][4];
        #pragma unroll
        for (int kk = 0; kk < 4; kk++) {
            pa[kk][0] = f2bf2(sc[2 * kk][0],     sc[2 * kk][1]);
            pa[kk][1] = f2bf2(sc[2 * kk][2],     sc[2 * kk][3]);
            pa[kk][2] = f2bf2(sc[2 * kk + 1][0], sc[2 * kk + 1][1]);
            pa[kk][3] = f2bf2(sc[2 * kk + 1][2], sc[2 * kk + 1][3]);
        }

        // O += P V : o[nd] covers d nd*8..nd*8+7
        #pragma unroll
        for (int db2 = 0; db2 < 4; db2++) {
            #pragma unroll
            for (int kk = 0; kk < 4; kk++) {
                int row = kk * 16 + vrow_off;
                int ch = db2 * 2 + gHi;
                uint32_t b0, b1, b2, b3;
                ldmx4t(b0, b1, b2, b3, vbase + row * 128 + (((ch ^ (row & 7)) & 7) << 4));
                mma16816(o[2 * db2],     pa[kk], b0, b1);
                mma16816(o[2 * db2 + 1], pa[kk], b2, b3);
            }
        }
        __syncthreads();
    }

    // final normalize + store fp32 token-major [b][n][c]
    rsum0 += __shfl_xor_sync(0xffffffffu, rsum0, 1);
    rsum0 += __shfl_xor_sync(0xffffffffu, rsum0, 2);
    rsum1 += __shfl_xor_sync(0xffffffffu, rsum1, 1);
    rsum1 += __shfl_xor_sync(0xffffffffu, rsum1, 2);
    float inv0 = 1.f / rsum0, inv1 = 1.f / rsum1;
    int g = lane >> 2, qo = (lane & 3) * 2;
    int row0 = qn0 + w * 16 + g, row1 = row0 + 8;
    float* d0p = g_ao + ((size_t)b * NTOK + row0) * C + h * HD + qo;
    float* d1p = g_ao + ((size_t)b * NTOK + row1) * C + h * HD + qo;
    #pragma unroll
    for (int nb = 0; nb < 8; nb++) {
        *reinterpret_cast<float2*>(d0p + nb * 8) = make_float2(o[nb][0] * inv0, o[nb][1] * inv0);
        *reinterpret_cast<float2*>(d1p + nb * 8) = make_float2(o[nb][2] * inv1, o[nb][3] * inv1);
    }
}

// ---------------- kernel D: proj GEMM + bias + residual (fp32) ----------------
__global__ __launch_bounds__(256) void proj_kernel(const float* __restrict__ x,
                                                   const float* __restrict__ W,
                                                   const float* __restrict__ bias,
                                                   float* __restrict__ out) {
    __shared__ float As[4096];
    __shared__ float Ws[4096];
    int tid = threadIdx.x;
    int tx = tid & 15, ty = tid >> 4;
    int n0 = blockIdx.x * 64, o0 = blockIdx.y * 64, b = blockIdx.z;
    float acc[4][4] = {};

    for (int c0 = 0; c0 < C; c0 += 64) {
        for (int i = tid; i < 1024; i += 256) {
            int r = i >> 4, c4 = i & 15;
            *reinterpret_cast<float4*>(As + SWZ(r, c4)) =
                *reinterpret_cast<const float4*>(g_ao + ((size_t)b * NTOK + n0 + r) * C + c0 + (c4 << 2));
            *reinterpret_cast<float4*>(Ws + SWZ(r, c4)) =
                *reinterpret_cast<const float4*>(W + (size_t)(o0 + r) * C + c0 + (c4 << 2));
        }
        __syncthreads();
        #pragma unroll
        for (int c4 = 0; c4 < 16; c4++) {
            float4 af[4], wf[4];
            #pragma unroll
            for (int r = 0; r < 4; r++)
                af[r] = *reinterpret_cast<const float4*>(As + SWZ((ty << 2) + r, c4));
            #pragma unroll
            for (int c = 0; c < 4; c++)
                wf[c] = *reinterpret_cast<const float4*>(Ws + SWZ((tx << 2) + c, c4));
            #pragma unroll
            for (int r = 0; r < 4; r++)
                #pragma unroll
                for (int c = 0; c < 4; c++)
                    acc[r][c] = fmaf(af[r].x, wf[c].x,
                                fmaf(af[r].y, wf[c].y,
                                fmaf(af[r].z, wf[c].z,
                                fmaf(af[r].w, wf[c].w, acc[r][c]))));
        }
        __syncthreads();
    }

    #pragma unroll
    for (int c = 0; c < 4; c++) {
        int o = o0 + (tx << 2) + c;
        float pb = bias[o];
        size_t idx = ((size_t)b * C + o) * NTOK + n0 + (ty << 2);
        float4 xv = *reinterpret_cast<const float4*>(x + idx);
        float4 ov = make_float4(acc[0][c] + pb + xv.x, acc[1][c] + pb + xv.y,
                                acc[2][c] + pb + xv.z, acc[3][c] + pb + xv.w);
        *reinterpret_cast<float4*>(out + idx) = ov;
    }
}

// ---------------- launch ----------------
extern "C" void kernel_launch(void* const* d_in, const int* in_sizes, int n_in,
                              void* d_out, int out_size) {
    const float* x      = (const float*)d_in[0];
    const float* norm_w = (const float*)d_in[1];
    const float* norm_b = (const float*)d_in[2];
    const float* qkv_w  = (const float*)d_in[3];
    const float* qkv_b  = (const float*)d_in[4];
    const float* proj_w = (const float*)d_in[5];
    const float* proj_b = (const float*)d_in[6];
    float* out = (float*)d_out;

    gn_stats_kernel<<<Bsz * G, 256>>>(x, norm_w, norm_b);
    qkv_kernel<<<dim3(NTOK / 64, (3 * C) / 64, Bsz), 256>>>(x, qkv_w, qkv_b);
    attn_kernel<<<dim3(NTOK / 128, Bsz * NH), 256>>>();
    proj_kernel<<<dim3(NTOK / 64, C / 64, Bsz), 256>>>(x, proj_w, proj_b, out);
}

// round 3
// speedup vs baseline: 6.4383x; 1.5634x over previous
#include <cuda_runtime.h>
#include <math.h>
#include <stdint.h>

#define Bsz 2
#define C 256
#define NTOK 4096
#define G 8
#define CPG 32
#define NH 4
#define HD 64
#define EPS 1e-5f
#define SCALE 0.125f
#define LOG2E 1.4426950408889634f

// ---------------- scratch (device globals) ----------------
__device__ uint16_t g_qkv[(size_t)Bsz * 3 * NH * NTOK * HD];  // bf16 [b][qkv][h][n][d]
__device__ uint16_t g_xn [(size_t)Bsz * NTOK * C];            // bf16 [b][n][c] normalized x
__device__ uint16_t g_ao [(size_t)Bsz * NTOK * C];            // bf16 [b][n][c] attn out
__device__ float    g_sA [Bsz * C];
__device__ float    g_tA [Bsz * C];

// ---------------- PTX helpers ----------------
__device__ __forceinline__ uint32_t f2bf2(float lo, float hi) {
    uint32_t r;
    asm("cvt.rn.bf16x2.f32 %0, %1, %2;" : "=r"(r) : "f"(hi), "f"(lo));
    return r;
}
__device__ __forceinline__ float ex2(float x) {
    float y; asm("ex2.approx.ftz.f32 %0, %1;" : "=f"(y) : "f"(x)); return y;
}
__device__ __forceinline__ void ldmx4(uint32_t& r0, uint32_t& r1, uint32_t& r2, uint32_t& r3,
                                      uint32_t addr) {
    asm volatile("ldmatrix.sync.aligned.m8n8.x4.shared.b16 {%0,%1,%2,%3}, [%4];"
                 : "=r"(r0), "=r"(r1), "=r"(r2), "=r"(r3) : "r"(addr));
}
__device__ __forceinline__ void ldmx4t(uint32_t& r0, uint32_t& r1, uint32_t& r2, uint32_t& r3,
                                       uint32_t addr) {
    asm volatile("ldmatrix.sync.aligned.m8n8.x4.trans.shared.b16 {%0,%1,%2,%3}, [%4];"
                 : "=r"(r0), "=r"(r1), "=r"(r2), "=r"(r3) : "r"(addr));
}
__device__ __forceinline__ void mma16816(float* c, const uint32_t* a, uint32_t b0, uint32_t b1) {
    asm volatile(
        "mma.sync.aligned.m16n8k16.row.col.f32.bf16.bf16.f32 "
        "{%0,%1,%2,%3}, {%4,%5,%6,%7}, {%8,%9}, {%0,%1,%2,%3};"
        : "+f"(c[0]), "+f"(c[1]), "+f"(c[2]), "+f"(c[3])
        : "r"(a[0]), "r"(a[1]), "r"(a[2]), "r"(a[3]), "r"(b0), "r"(b1));
}

// ---------------- kernel A: groupnorm stats + affine coefficients ----------------
__global__ void gn_stats_kernel(const float* __restrict__ x,
                                const float* __restrict__ nw,
                                const float* __restrict__ nb) {
    int bg = blockIdx.x;
    int tid = threadIdx.x;
    const float4* p = reinterpret_cast<const float4*>(x + (size_t)bg * (CPG * NTOK));
    float s = 0.f, ss = 0.f;
    const int n4 = (CPG * NTOK) / 4;
    for (int i = tid; i < n4; i += 256) {
        float4 v = p[i];
        s  += v.x + v.y + v.z + v.w;
        ss += v.x * v.x + v.y * v.y + v.z * v.z + v.w * v.w;
    }
    #pragma unroll
    for (int o = 16; o > 0; o >>= 1) {
        s  += __shfl_xor_sync(0xffffffffu, s, o);
        ss += __shfl_xor_sync(0xffffffffu, ss, o);
    }
    __shared__ float rs[8], rss[8];
    __shared__ float sh_mean, sh_rstd;
    if ((tid & 31) == 0) { rs[tid >> 5] = s; rss[tid >> 5] = ss; }
    __syncthreads();
    if (tid == 0) {
        float S = 0.f, SS = 0.f;
        #pragma unroll
        for (int i = 0; i < 8; i++) { S += rs[i]; SS += rss[i]; }
        const float inv = 1.f / (float)(CPG * NTOK);
        float mean = S * inv;
        float var  = SS * inv - mean * mean;
        sh_mean = mean;
        sh_rstd = rsqrtf(var + EPS);
    }
    __syncthreads();
    if (tid < CPG) {
        int b = bg / G, g = bg % G;
        int c = g * CPG + tid;
        float sA = sh_rstd * nw[c];
        g_sA[b * C + c] = sA;
        g_tA[b * C + c] = nb[c] - sh_mean * sA;
    }
}

// ---------------- kernel A2: normalize + transpose x -> bf16 token-major ----------
// x[b][c][n] fp32 -> g_xn[b][n][c] bf16, 64ch x 64tok tiles
__global__ __launch_bounds__(256) void xn_kernel(const float* __restrict__ x) {
    __shared__ uint16_t Ts[64][72];   // [ch][token], row stride 72 (144B)
    int tid = threadIdx.x;
    int b = blockIdx.z, c0 = blockIdx.y * 64, n0 = blockIdx.x * 64;
    #pragma unroll
    for (int p = 0; p < 4; p++) {
        int i = p * 256 + tid;
        int ch = i >> 4, t4 = (i & 15) << 2;
        float sA = g_sA[b * C + c0 + ch], tA = g_tA[b * C + c0 + ch];
        float4 v = *reinterpret_cast<const float4*>(x + ((size_t)b * C + c0 + ch) * NTOK + n0 + t4);
        uint2 u = make_uint2(f2bf2(fmaf(v.x, sA, tA), fmaf(v.y, sA, tA)),
                             f2bf2(fmaf(v.z, sA, tA), fmaf(v.w, sA, tA)));
        *reinterpret_cast<uint2*>(&Ts[ch][t4]) = u;
    }
    __syncthreads();
    #pragma unroll
    for (int p = 0; p < 2; p++) {
        int i = p * 256 + tid;
        int tok = i >> 3, chk = i & 7;
        uint16_t tmp[8];
        #pragma unroll
        for (int j = 0; j < 8; j++) tmp[j] = Ts[chk * 8 + j][tok];
        *reinterpret_cast<uint4*>(g_xn + ((size_t)b * NTOK + n0 + tok) * C + c0 + chk * 8) =
            *reinterpret_cast<uint4*>(tmp);
    }
}

// ---------------- kernel B: QKV GEMM bf16 mma (A=g_xn, B=qkv_w) --------------------
// CTA: 128 tokens x 64 outch, K staged 64x4. Warp: 32tok x 32outch.
__global__ __launch_bounds__(256) void qkv_kernel(const float* __restrict__ W,
                                                  const float* __restrict__ bias) {
    __shared__ __align__(16) uint16_t As[128 * 64];  // [token][ch] swizzled 128B rows
    __shared__ __align__(16) uint16_t Bs2[64 * 64];  // [outch][ch] swizzled
    int tid = threadIdx.x;
    int w = tid >> 5, lane = tid & 31;
    int l8 = lane & 7, ggg = lane >> 3;
    int gLo = ggg & 1, gHi = ggg >> 1;
    int wm = (w & 3) * 32, wn = (w >> 2) * 32;
    int n0 = blockIdx.x * 128, m0 = blockIdx.y * 64, b = blockIdx.z;

    uint32_t abase = (uint32_t)__cvta_generic_to_shared(As);
    uint32_t bbase = (uint32_t)__cvta_generic_to_shared(Bs2);
    float acc[2][4][4] = {};

    for (int k0 = 0; k0 < C; k0 += 64) {
        #pragma unroll
        for (int p = 0; p < 4; p++) {
            int i = p * 256 + tid;
            int r = i >> 3, ch = i & 7;
            *reinterpret_cast<uint4*>((char*)As + r * 128 + (((ch ^ (r & 7)) & 7) << 4)) =
                *reinterpret_cast<const uint4*>(g_xn + ((size_t)b * NTOK + n0 + r) * C + k0 + ch * 8);
        }
        #pragma unroll
        for (int p = 0; p < 2; p++) {
            int i = p * 256 + tid;
            int r = i >> 3, ch = i & 7;
            const float* wp = W + (size_t)(m0 + r) * C + k0 + ch * 8;
            float4 w0 = *reinterpret_cast<const float4*>(wp);
            float4 w1 = *reinterpret_cast<const float4*>(wp + 4);
            uint4 u = make_uint4(f2bf2(w0.x, w0.y), f2bf2(w0.z, w0.w),
                                 f2bf2(w1.x, w1.y), f2bf2(w1.z, w1.w));
            *reinterpret_cast<uint4*>((char*)Bs2 + r * 128 + (((ch ^ (r & 7)) & 7) << 4)) = u;
        }
        __syncthreads();
        #pragma unroll
        for (int kk = 0; kk < 4; kk++) {
            uint32_t af[2][4];
            #pragma unroll
            for (int i = 0; i < 2; i++) {
                int row = wm + i * 16 + gLo * 8 + l8;
                int ch = kk * 2 + gHi;
                ldmx4(af[i][0], af[i][1], af[i][2], af[i][3],
                      abase + row * 128 + (((ch ^ (row & 7)) & 7) << 4));
            }
            #pragma unroll
            for (int j2 = 0; j2 < 2; j2++) {
                int row = wn + j2 * 16 + gHi * 8 + l8;
                int ch = kk * 2 + gLo;
                uint32_t b0, b1, b2, b3;
                ldmx4(b0, b1, b2, b3, bbase + row * 128 + (((ch ^ (row & 7)) & 7) << 4));
                #pragma unroll
                for (int i = 0; i < 2; i++) {
                    mma16816(acc[i][2 * j2],     af[i], b0, b1);
                    mma16816(acc[i][2 * j2 + 1], af[i], b2, b3);
                }
            }
        }
        __syncthreads();
    }

    // epilogue: bias (+ q log2-domain scale), bf16 token-major store
    int which = blockIdx.y >> 2;
    int h     = blockIdx.y & 3;
    float qs = (which == 0) ? (SCALE * LOG2E) : 1.f;
    int g = lane >> 2, colq = (lane & 3) * 2;
    size_t base = ((size_t)(b * 3 + which) * NH + h) * NTOK;
    #pragma unroll
    for (int i = 0; i < 2; i++) {
        int tok0 = n0 + wm + i * 16 + g;
        #pragma unroll
        for (int j = 0; j < 4; j++) {
            int d = wn + j * 8 + colq;
            float pb0 = bias[m0 + d], pb1 = bias[m0 + d + 1];
            *reinterpret_cast<uint32_t*>(g_qkv + (base + tok0) * HD + d) =
                f2bf2((acc[i][j][0] + pb0) * qs, (acc[i][j][1] + pb1) * qs);
            *reinterpret_cast<uint32_t*>(g_qkv + (base + tok0 + 8) * HD + d) =
                f2bf2((acc[i][j][2] + pb0) * qs, (acc[i][j][3] + pb1) * qs);
        }
    }
}

// ---------------- kernel C: flash attention (bf16 mma, online softmax) -------------
__global__ __launch_bounds__(256, 2) void attn_kernel() {
    __shared__ __align__(16) uint16_t Ks[64 * 64];
    __shared__ __align__(16) uint16_t Vs[64 * 64];
    __shared__ __align__(16) uint16_t Qs[128 * 64];
    int tid = threadIdx.x;
    int w = tid >> 5, lane = tid & 31;
    int qn0 = blockIdx.x * 128;
    int b = blockIdx.y >> 2, h = blockIdx.y & 3;

    const uint16_t* qg = g_qkv + (((size_t)(b * 3 + 0) * NH + h) * NTOK + qn0) * HD;
    const uint16_t* kg = g_qkv + (((size_t)(b * 3 + 1) * NH + h) * NTOK) * HD;
    const uint16_t* vg = g_qkv + (((size_t)(b * 3 + 2) * NH + h) * NTOK) * HD;

    for (int i = tid; i < 1024; i += 256) {
        int r = i >> 3, ch = i & 7;
        uint4 v = *reinterpret_cast<const uint4*>(qg + r * 64 + ch * 8);
        *reinterpret_cast<uint4*>((char*)Qs + r * 128 + (((ch ^ (r & 7)) & 7) << 4)) = v;
    }
    __syncthreads();

    uint32_t qbase = (uint32_t)__cvta_generic_to_shared(Qs);
    uint32_t kbase = (uint32_t)__cvta_generic_to_shared(Ks);
    uint32_t vbase = (uint32_t)__cvta_generic_to_shared(Vs);
    int l8 = lane & 7, ggg = lane >> 3;
    int gLo = ggg & 1, gHi = ggg >> 1;

    uint32_t qf[4][4];
    {
        int row = w * 16 + gLo * 8 + l8;
        #pragma unroll
        for (int kk = 0; kk < 4; kk++) {
            int ch = kk * 2 + gHi;
            ldmx4(qf[kk][0], qf[kk][1], qf[kk][2], qf[kk][3],
                  qbase + row * 128 + (((ch ^ (row & 7)) & 7) << 4));
        }
    }
    __syncthreads();

    int krow_off = gHi * 8 + l8;
    int vrow_off = gLo * 8 + l8;

    float o[8][4] = {};
    float rmax0 = -1e30f, rmax1 = -1e30f, rsum0 = 0.f, rsum1 = 0.f;

    for (int kt = 0; kt < NTOK / 64; kt++) {
        const uint16_t* kp = kg + (size_t)kt * 64 * 64;
        const uint16_t* vp = vg + (size_t)kt * 64 * 64;
        for (int i = tid; i < 512; i += 256) {
            int r = i >> 3, ch = i & 7;
            int so = r * 128 + (((ch ^ (r & 7)) & 7) << 4);
            *reinterpret_cast<uint4*>((char*)Ks + so) =
                *reinterpret_cast<const uint4*>(kp + r * 64 + ch * 8);
            *reinterpret_cast<uint4*>((char*)Vs + so) =
                *reinterpret_cast<const uint4*>(vp + r * 64 + ch * 8);
        }
        __syncthreads();

        float sc[8][4] = {};
        #pragma unroll
        for (int nb2 = 0; nb2 < 4; nb2++) {
            #pragma unroll
            for (int kk = 0; kk < 4; kk++) {
                int row = nb2 * 16 + krow_off;
                int ch = kk * 2 + gLo;
                uint32_t b0, b1, b2, b3;
                ldmx4(b0, b1, b2, b3, kbase + row * 128 + (((ch ^ (row & 7)) & 7) << 4));
                mma16816(sc[2 * nb2],     qf[kk], b0, b1);
                mma16816(sc[2 * nb2 + 1], qf[kk], b2, b3);
            }
        }

        float m0 = -1e30f, m1 = -1e30f;
        #pragma unroll
        for (int nb = 0; nb < 8; nb++) {
            m0 = fmaxf(m0, fmaxf(sc[nb][0], sc[nb][1]));
            m1 = fmaxf(m1, fmaxf(sc[nb][2], sc[nb][3]));
        }
        m0 = fmaxf(m0, __shfl_xor_sync(0xffffffffu, m0, 1));
        m0 = fmaxf(m0, __shfl_xor_sync(0xffffffffu, m0, 2));
        m1 = fmaxf(m1, __shfl_xor_sync(0xffffffffu, m1, 1));
        m1 = fmaxf(m1, __shfl_xor_sync(0xffffffffu, m1, 2));
        float mn0 = fmaxf(rmax0, m0), mn1 = fmaxf(rmax1, m1);
        float al0 = ex2(rmax0 - mn0), al1 = ex2(rmax1 - mn1);
        rmax0 = mn0; rmax1 = mn1;
        float ps0 = 0.f, ps1 = 0.f;
        #pragma unroll
        for (int nb = 0; nb < 8; nb++) {
            sc[nb][0] = ex2(sc[nb][0] - mn0);
            sc[nb][1] = ex2(sc[nb][1] - mn0);
            sc[nb][2] = ex2(sc[nb][2] - mn1);
            sc[nb][3] = ex2(sc[nb][3] - mn1);
            ps0 += sc[nb][0] + sc[nb][1];
            ps1 += sc[nb][2] + sc[nb][3];
            o[nb][0] *= al0; o[nb][1] *= al0;
            o[nb][2] *= al1; o[nb][3] *= al1;
        }
        rsum0 = rsum0 * al0 + ps0;
        rsum1 = rsum1 * al1 + ps1;

        uint32_t pa[4][4];
        #pragma unroll
        for (int kk = 0; kk < 4; kk++) {
            pa[kk][0] = f2bf2(sc[2 * kk][0],     sc[2 * kk][1]);
            pa[kk][1] = f2bf2(sc[2 * kk][2],     sc[2 * kk][3]);
            pa[kk][2] = f2bf2(sc[2 * kk + 1][0], sc[2 * kk + 1][1]);
            pa[kk][3] = f2bf2(sc[2 * kk + 1][2], sc[2 * kk + 1][3]);
        }

        #pragma unroll
        for (int db2 = 0; db2 < 4; db2++) {
            #pragma unroll
            for (int kk = 0; kk < 4; kk++) {
                int row = kk * 16 + vrow_off;
                int ch = db2 * 2 + gHi;
                uint32_t b0, b1, b2, b3;
                ldmx4t(b0, b1, b2, b3, vbase + row * 128 + (((ch ^ (row & 7)) & 7) << 4));
                mma16816(o[2 * db2],     pa[kk], b0, b1);
                mma16816(o[2 * db2 + 1], pa[kk], b2, b3);
            }
        }
        __syncthreads();
    }

    rsum0 += __shfl_xor_sync(0xffffffffu, rsum0, 1);
    rsum0 += __shfl_xor_sync(0xffffffffu, rsum0, 2);
    rsum1 += __shfl_xor_sync(0xffffffffu, rsum1, 1);
    rsum1 += __shfl_xor_sync(0xffffffffu, rsum1, 2);
    float inv0 = 1.f / rsum0, inv1 = 1.f / rsum1;
    int g = lane >> 2, qo = (lane & 3) * 2;
    int row0 = qn0 + w * 16 + g, row1 = row0 + 8;
    uint16_t* d0p = g_ao + ((size_t)b * NTOK + row0) * C + h * HD + qo;
    uint16_t* d1p = g_ao + ((size_t)b * NTOK + row1) * C + h * HD + qo;
    #pragma unroll
    for (int nb = 0; nb < 8; nb++) {
        *reinterpret_cast<uint32_t*>(d0p + nb * 8) = f2bf2(o[nb][0] * inv0, o[nb][1] * inv0);
        *reinterpret_cast<uint32_t*>(d1p + nb * 8) = f2bf2(o[nb][2] * inv1, o[nb][3] * inv1);
    }
}

// ---------------- kernel D: proj GEMM bf16 mma + bias + residual -------------------
__global__ __launch_bounds__(256) void proj_kernel(const float* __restrict__ x,
                                                   const float* __restrict__ W,
                                                   const float* __restrict__ bias,
                                                   float* __restrict__ out) {
    __shared__ __align__(16) uint16_t As[128 * 64];
    __shared__ __align__(16) uint16_t Bs2[64 * 64];
    int tid = threadIdx.x;
    int w = tid >> 5, lane = tid & 31;
    int l8 = lane & 7, ggg = lane >> 3;
    int gLo = ggg & 1, gHi = ggg >> 1;
    int wm = (w & 3) * 32, wn = (w >> 2) * 32;
    int n0 = blockIdx.x * 128, o0 = blockIdx.y * 64, b = blockIdx.z;

    uint32_t abase = (uint32_t)__cvta_generic_to_shared(As);
    uint32_t bbase = (uint32_t)__cvta_generic_to_shared(Bs2);
    float acc[2][4][4] = {};

    for (int k0 = 0; k0 < C; k0 += 64) {
        #pragma unroll
        for (int p = 0; p < 4; p++) {
            int i = p * 256 + tid;
            int r = i >> 3, ch = i & 7;
            *reinterpret_cast<uint4*>((char*)As + r * 128 + (((ch ^ (r & 7)) & 7) << 4)) =
                *reinterpret_cast<const uint4*>(g_ao + ((size_t)b * NTOK + n0 + r) * C + k0 + ch * 8);
        }
        #pragma unroll
        for (int p = 0; p < 2; p++) {
            int i = p * 256 + tid;
            int r = i >> 3, ch = i & 7;
            const float* wp = W + (size_t)(o0 + r) * C + k0 + ch * 8;
            float4 w0 = *reinterpret_cast<const float4*>(wp);
            float4 w1 = *reinterpret_cast<const float4*>(wp + 4);
            uint4 u = make_uint4(f2bf2(w0.x, w0.y), f2bf2(w0.z, w0.w),
                                 f2bf2(w1.x, w1.y), f2bf2(w1.z, w1.w));
            *reinterpret_cast<uint4*>((char*)Bs2 + r * 128 + (((ch ^ (r & 7)) & 7) << 4)) = u;
        }
        __syncthreads();
        #pragma unroll
        for (int kk = 0; kk < 4; kk++) {
            uint32_t af[2][4];
            #pragma unroll
            for (int i = 0; i < 2; i++) {
                int row = wm + i * 16 + gLo * 8 + l8;
                int ch = kk * 2 + gHi;
                ldmx4(af[i][0], af[i][1], af[i][2], af[i][3],
                      abase + row * 128 + (((ch ^ (row & 7)) & 7) << 4));
            }
            #pragma unroll
            for (int j2 = 0; j2 < 2; j2++) {
                int row = wn + j2 * 16 + gHi * 8 + l8;
                int ch = kk * 2 + gLo;
                uint32_t b0, b1, b2, b3;
                ldmx4(b0, b1, b2, b3, bbase + row * 128 + (((ch ^ (row & 7)) & 7) << 4));
                #pragma unroll
                for (int i = 0; i < 2; i++) {
                    mma16816(acc[i][2 * j2],     af[i], b0, b1);
                    mma16816(acc[i][2 * j2 + 1], af[i], b2, b3);
                }
            }
        }
        __syncthreads();
    }

    // epilogue: fp32 bias + residual, channel-major out
    int g = lane >> 2, colq = (lane & 3) * 2;
    #pragma unroll
    for (int i = 0; i < 2; i++) {
        int tok0 = n0 + wm + i * 16 + g;
        #pragma unroll
        for (int j = 0; j < 4; j++) {
            int o = o0 + wn + j * 8 + colq;
            float pb0 = bias[o], pb1 = bias[o + 1];
            size_t i00 = ((size_t)b * C + o) * NTOK + tok0;
            size_t i10 = i00 + NTOK;          // o+1, tok0
            out[i00]     = acc[i][j][0] + pb0 + x[i00];
            out[i10]     = acc[i][j][1] + pb1 + x[i10];
            out[i00 + 8] = acc[i][j][2] + pb0 + x[i00 + 8];
            out[i10 + 8] = acc[i][j][3] + pb1 + x[i10 + 8];
        }
    }
}

// ---------------- launch ----------------
extern "C" void kernel_launch(void* const* d_in, const int* in_sizes, int n_in,
                              void* d_out, int out_size) {
    const float* x      = (const float*)d_in[0];
    const float* norm_w = (const float*)d_in[1];
    const float* norm_b = (const float*)d_in[2];
    const float* qkv_w  = (const float*)d_in[3];
    const float* qkv_b  = (const float*)d_in[4];
    const float* proj_w = (const float*)d_in[5];
    const float* proj_b = (const float*)d_in[6];
    float* out = (float*)d_out;

    gn_stats_kernel<<<Bsz * G, 256>>>(x, norm_w, norm_b);
    xn_kernel<<<dim3(NTOK / 64, C / 64, Bsz), 256>>>(x);
    qkv_kernel<<<dim3(NTOK / 128, (3 * C) / 64, Bsz), 256>>>(qkv_w, qkv_b);
    attn_kernel<<<dim3(NTOK / 128, Bsz * NH), 256>>>();
    proj_kernel<<<dim3(NTOK / 128, C / 64, Bsz), 256>>>(x, proj_w, proj_b, out);
}